// round 5
// baseline (speedup 1.0000x reference)
#include <cuda_runtime.h>
#include <math.h>

#define BB 16
#define NN 2304
#define HH 48
#define CIN 256
#define GM 1024

__device__ float  g_xf[BB*NN*64];
__device__ float  g_x2[BB*NN];
__device__ float2 g_tsp[64*32];
__device__ float  g_c0[64], g_c1[64], g_c2[64];
__device__ float  g_P[GM*NN];
__device__ float  g_M[BB*64*64];
__device__ float  g_colsum[GM], g_S[GM], g_pisum[GM];
__device__ float  g_T[HH*HH];
__device__ float  g_rcol[NN];
__device__ float  g_Amask[NN*NN];
__device__ float  g_Y1[GM*NN];
__device__ float  g_Y2[GM*NN];

__device__ __forceinline__ float2 ffma2(float2 a, float2 b, float2 c) {
    union { float2 f; unsigned long long u; } ua, ub, uc, ud;
    ua.f = a; ub.f = b; uc.f = c;
    asm("fma.rn.f32x2 %0, %1, %2, %3;" : "=l"(ud.u) : "l"(ua.u), "l"(ub.u), "l"(uc.u));
    return ud.f;
}

__global__ void k_zero() {
    int i = blockIdx.x*256 + threadIdx.x;
    if (i < BB*64*64) g_M[i] = 0.f;
    else { int j = i - BB*64*64;
        if (j < GM) g_colsum[j] = 0.f;
        else if (j < 2*GM) g_S[j-GM] = 0.f;
        else if (j < 3*GM) g_pisum[j-2*GM] = 0.f; }
}

__global__ void k_tmpl(const float* __restrict__ clus, const float* __restrict__ pi,
                       const float* __restrict__ cov, const float* __restrict__ nts,
                       const float* __restrict__ ntb) {
    __shared__ float ts[64][65];
    int tid = threadIdx.x, w = tid>>5, lane = tid&31;
    for (int q = 0; q < 8; q++) {
        int k = w*8 + q;
        float v0 = clus[k*64+lane], v1 = clus[k*64+lane+32];
        float s = v0+v1;
        for (int o=16;o>0;o>>=1) s += __shfl_xor_sync(~0u,s,o);
        float mean = s*(1.f/64.f), d0 = v0-mean, d1 = v1-mean;
        float vs = d0*d0 + d1*d1;
        for (int o=16;o>0;o>>=1) vs += __shfl_xor_sync(~0u,vs,o);
        float rstd = rsqrtf(vs*(1.f/64.f) + 1e-5f);
        ts[k][lane]    = d0*rstd*nts[lane]    + ntb[lane];
        ts[k][lane+32] = d1*rstd*nts[lane+32] + ntb[lane+32];
    }
    __syncthreads();
    if (tid < 64) {
        float t2 = 0.f;
        for (int c = 0; c < 64; c++) { float v = ts[tid][c]; t2 = fmaf(v,v,t2); }
        float cv = cov[tid], c1 = 1.f/cv, c2 = 0.5f*c1;
        g_c1[tid] = c1; g_c2[tid] = c2;
        g_c0[tid] = logf(pi[tid]/sqrtf(cv)) - t2*c2;
    }
    __syncthreads();
    for (int j = 0; j < 8; j++) {
        int idx = tid + 256*j, c = idx>>5, l = idx&31;
        g_tsp[c*32+l] = make_float2(ts[l][c], ts[l+32][c]);
    }
}

__global__ __launch_bounds__(256)
void k_proj(const float* __restrict__ x, const float* __restrict__ w) {
    int b = blockIdx.y, n0 = blockIdx.x*128;
    __shared__ float Xs[16][128], Ws[64][20], xfs[128][65];
    int tid = threadIdx.x, tn = tid&31, tc = tid>>5;
    float acc[4][8];
    for (int q=0;q<4;q++) for (int r=0;r<8;r++) acc[q][r] = 0.f;
    const float* xb = x + ((size_t)b*CIN)*NN + n0;
    for (int it = 0; it < CIN/16; it++) {
        for (int j = 0; j < 2; j++) {
            int idx = tid + 256*j, r = idx>>5, c = (idx&31)<<2;
            *(float4*)&Xs[r][c] = *(const float4*)&xb[(it*16+r)*NN + c];
        }
        { int r = tid>>2, c = (tid&3)<<2;
          *(float4*)&Ws[r][c] = *(const float4*)&w[r*CIN + it*16 + c]; }
        __syncthreads();
        for (int ii = 0; ii < 16; ii++) {
            float xv[4], wv[8];
            for (int q=0;q<4;q++) xv[q] = Xs[ii][tn+32*q];
            for (int r=0;r<8;r++) wv[r] = Ws[tc+8*r][ii];
            for (int q=0;q<4;q++) for (int r=0;r<8;r++) acc[q][r] = fmaf(xv[q],wv[r],acc[q][r]);
        }
        __syncthreads();
    }
    for (int q=0;q<4;q++) for (int r=0;r<8;r++) xfs[tn+32*q][tc+8*r] = acc[q][r];
    __syncthreads();
    if (tid < 128) {
        float s = 0.f;
        for (int c = 0; c < 64; c++) { float v = xfs[tid][c]; s = fmaf(v,v,s); }
        g_x2[b*NN + n0 + tid] = s;
    }
    float* xfg = g_xf + (size_t)(b*NN+n0)*64;
    for (int j = 0; j < 32; j++) { int idx = tid + 256*j; xfg[idx] = xfs[idx>>6][idx&63]; }
}

__global__ __launch_bounds__(256)
void k_softmax(float* __restrict__ attn_out) {
    int b = blockIdx.y, n0 = blockIdx.x*32;
    __shared__ float xfs[32][64];
    __shared__ float2 tsp_s[64][32];
    __shared__ float attn_s[64][33], x2s[32], c0s[64], c1s[64], c2s[64];
    int tid = threadIdx.x;
    if (tid < 64) { c0s[tid]=g_c0[tid]; c1s[tid]=g_c1[tid]; c2s[tid]=g_c2[tid]; }
    if (tid < 32) x2s[tid] = g_x2[b*NN+n0+tid];
    { const float4* s = (const float4*)g_tsp; float4* d = (float4*)tsp_s;
      for (int j=0;j<4;j++) d[tid+256*j] = s[tid+256*j]; }
    { const float4* s = (const float4*)(g_xf + (size_t)(b*NN+n0)*64); float4* d = (float4*)xfs;
      d[tid] = s[tid]; d[tid+256] = s[tid+256]; }
    __syncthreads();
    int w = tid>>5, lane = tid&31;
    for (int q = 0; q < 4; q++) {
        int nl = w*4 + q;
        float x2v = x2s[nl], a0 = 0.f, a1 = 0.f;
        for (int c = 0; c < 64; c++) {
            float xc = xfs[nl][c]; float2 tv = tsp_s[c][lane];
            a0 = fmaf(xc, tv.x, a0); a1 = fmaf(xc, tv.y, a1);
        }
        float g0 = c0s[lane]    + a0*c1s[lane]    - x2v*c2s[lane];
        float g1 = c0s[lane+32] + a1*c1s[lane+32] - x2v*c2s[lane+32];
        float mx = fmaxf(g0, g1);
        for (int o=16;o>0;o>>=1) mx = fmaxf(mx, __shfl_xor_sync(~0u,mx,o));
        float e0 = __expf(g0-mx), e1 = __expf(g1-mx), s = e0+e1;
        for (int o=16;o>0;o>>=1) s += __shfl_xor_sync(~0u,s,o);
        float r = 1.f/s;
        attn_s[lane][nl] = e0*r; attn_s[lane+32][nl] = e1*r;
    }
    __syncthreads();
    if (tid < 64) {
        float cs = 0.f, ss = 0.f, ps = 0.f;
        for (int nl = 0; nl < 32; nl++) {
            float a = attn_s[tid][nl], ae = a + 1e-8f;
            ps += a; cs += ae; ss = fmaf(ae, x2s[nl], ss);
        }
        atomicAdd(&g_colsum[b*64+tid], cs);
        atomicAdd(&g_S[b*64+tid], ss);
        atomicAdd(&g_pisum[b*64+tid], ps);
    }
    float* pout = g_P + (size_t)(b*64)*NN + n0;
    float* aout = attn_out + (size_t)b*64*NN + n0;
    for (int j = 0; j < 8; j++) {
        int idx = tid + 256*j, k = idx>>5, ml = idx&31;
        float a = attn_s[k][ml];
        aout[(size_t)k*NN + ml] = a;
        pout[(size_t)k*NN + ml] = a + 1e-8f;
    }
}

__global__ __launch_bounds__(256)
void k_tnewgemm() {
    int b = blockIdx.y;
    __shared__ float Ps[64][33], Xs2[32][65];
    int tid = threadIdx.x, tx = tid&15, ty = tid>>4;
    float acc[4][4];
    for (int a=0;a<4;a++) for (int d=0;d<4;d++) acc[a][d] = 0.f;
    for (int st = 0; st < 8; st++) {
        int n0 = blockIdx.x*256 + st*32;
        for (int j = 0; j < 8; j++) {
            int idx = tid + 256*j;
            Ps[idx>>5][idx&31] = g_P[(size_t)(b*64 + (idx>>5))*NN + n0 + (idx&31)];
        }
        for (int j = 0; j < 8; j++) {
            int idx = tid + 256*j;
            Xs2[idx>>6][idx&63] = g_xf[((size_t)(b*NN+n0) + (idx>>6))*64 + (idx&63)];
        }
        __syncthreads();
        for (int nl = 0; nl < 32; nl++) {
            float kv[4], xv[4];
            for (int a=0;a<4;a++) kv[a] = Ps[ty+16*a][nl];
            for (int d=0;d<4;d++) xv[d] = Xs2[nl][tx+16*d];
            for (int a=0;a<4;a++) for (int d=0;d<4;d++) acc[a][d] = fmaf(kv[a],xv[d],acc[a][d]);
        }
        __syncthreads();
    }
    for (int a=0;a<4;a++) for (int d=0;d<4;d++)
        atomicAdd(&g_M[b*4096 + (ty+16*a)*64 + tx+16*d], acc[a][d]);
}

__global__ void k_stats(float* __restrict__ out_t, float* __restrict__ out_pi,
                        float* __restrict__ out_cov) {
    int b = blockIdx.x, k = threadIdx.x;
    float rc = 1.f/g_colsum[b*64+k], tn2 = 0.f;
    float* tout = out_t + (size_t)(b*64+k)*64;
    for (int c = 0; c < 64; c++) {
        float tv = g_M[b*4096 + k*64 + c]*rc;
        tout[c] = tv; tn2 = fmaf(tv,tv,tn2);
    }
    out_pi[b*64+k] = g_pisum[b*64+k]*(1.f/(float)NN);
    out_cov[b*64+k] = g_S[b*64+k]*rc - tn2;
}

__global__ void k_table() {
    int idx = blockIdx.x*256 + threadIdx.x;
    if (idx < HH*HH) {
        int di = idx/HH, dj = idx%HH;
        g_T[idx] = expf(-sqrtf((float)(di*di + dj*dj)));
    }
}

__global__ void k_mcol() {
    __shared__ float Ts[HH*HH], U[HH*HH];
    int tid = threadIdx.x;
    for (int i = tid; i < HH*HH; i += 256) Ts[i] = g_T[i];
    __syncthreads();
    for (int idx = tid; idx < HH*HH; idx += 256) {
        int di = idx/HH, jm = idx%HH; float s = 0.f;
        for (int j = 0; j < HH; j++) s += Ts[di*HH + abs(j-jm)];
        U[idx] = s;
    }
    __syncthreads();
    for (int idx = tid; idx < HH*HH; idx += 256) {
        int im = idx/HH, jm = idx%HH; float s = 0.f;
        for (int i = 0; i < HH; i++) s += U[abs(i-im)*HH + jm];
        g_rcol[idx] = 1.f/s;
    }
}

__global__ void k_buildA() {
    int n = blockIdx.y, m = blockIdx.x*256 + threadIdx.x;
    int ni = n/HH, nj = n - ni*HH, mi = m/HH, mj = m - mi*HH;
    g_Amask[(size_t)n*NN + m] = g_T[abs(ni-mi)*HH + abs(nj-mj)] * g_rcol[m];
}

__global__ __launch_bounds__(256, 1)
void k_sgemm(const float* __restrict__ A, const float* __restrict__ B, float* __restrict__ C) {
    __shared__ float2 As2[16][128];
    __shared__ float  Bs[16][128];
    int tid = threadIdx.x;
    int bm = blockIdx.y<<7, bn = blockIdx.x<<7;
    int ty = tid>>4, tx = tid&15;
    int ar = tid>>2, ac = (tid&3)<<2;
    int br = tid>>4, bc = (tid&15)<<3;
    const float* aptr = A + (size_t)(bm+ar)*NN + ac;
    const float* bptr = B + (size_t)br*NN + bn + bc;
    float2 acc[8][4];
    for (int i=0;i<8;i++) for (int j=0;j<4;j++) acc[i][j] = make_float2(0.f,0.f);
    for (int kt = 0; kt < NN/16; kt++) {
        float4 a0 = *(const float4*)(aptr + kt*16);
        float4 a1 = *(const float4*)(aptr + kt*16 + (size_t)64*NN);
        float4 b0 = *(const float4*)(bptr + (size_t)kt*16*NN);
        float4 b1 = *(const float4*)(bptr + (size_t)kt*16*NN + 4);
        As2[ac+0][ar] = make_float2(a0.x,a0.x); As2[ac+1][ar] = make_float2(a0.y,a0.y);
        As2[ac+2][ar] = make_float2(a0.z,a0.z); As2[ac+3][ar] = make_float2(a0.w,a0.w);
        As2[ac+0][ar+64] = make_float2(a1.x,a1.x); As2[ac+1][ar+64] = make_float2(a1.y,a1.y);
        As2[ac+2][ar+64] = make_float2(a1.z,a1.z); As2[ac+3][ar+64] = make_float2(a1.w,a1.w);
        *(float4*)&Bs[br][bc] = b0; *(float4*)&Bs[br][bc+4] = b1;
        __syncthreads();
#pragma unroll
        for (int kk = 0; kk < 16; kk++) {
            float4 af[4], bf0, bf1;
            for (int j=0;j<4;j++) af[j] = *(const float4*)&As2[kk][(ty<<3) + 2*j];
            bf0 = *(const float4*)&Bs[kk][tx<<3];
            bf1 = *(const float4*)&Bs[kk][(tx<<3)+4];
            float2 bv[4] = { {bf0.x,bf0.y}, {bf0.z,bf0.w}, {bf1.x,bf1.y}, {bf1.z,bf1.w} };
            for (int i2 = 0; i2 < 4; i2++) {
                float2 aL = make_float2(af[i2].x, af[i2].y);
                float2 aH = make_float2(af[i2].z, af[i2].w);
                for (int j = 0; j < 4; j++) {
                    acc[2*i2][j]   = ffma2(aL, bv[j], acc[2*i2][j]);
                    acc[2*i2+1][j] = ffma2(aH, bv[j], acc[2*i2+1][j]);
                }
            }
        }
        __syncthreads();
    }
    for (int i = 0; i < 8; i++) {
        float* crow = C + (size_t)(bm + (ty<<3) + i)*NN + bn + (tx<<3);
        ((float4*)crow)[0] = make_float4(acc[i][0].x,acc[i][0].y,acc[i][1].x,acc[i][1].y);
        ((float4*)crow)[1] = make_float4(acc[i][2].x,acc[i][2].y,acc[i][3].x,acc[i][3].y);
    }
}

__global__ __launch_bounds__(256)
void k_finalln(const float* __restrict__ pns, const float* __restrict__ pnb,
               float* __restrict__ outp) {
    int b = blockIdx.y, m0 = blockIdx.x*32;
    __shared__ float vs[64][33], rcs[64], sc[64], bi[64];
    int tid = threadIdx.x;
    if (tid < 64) { rcs[tid] = 1.f/g_colsum[b*64+tid]; sc[tid] = pns[tid]; bi[tid] = pnb[tid]; }
    __syncthreads();
    for (int j = 0; j < 8; j++) {
        int idx = tid + 256*j, k = idx>>5, ml = idx&31;
        vs[k][ml] = g_Y2[(size_t)(b*64+k)*NN + m0 + ml]*rcs[k];
    }
    __syncthreads();
    int w = tid>>5, lane = tid&31;
    for (int q = 0; q < 4; q++) {
        int ml = w*4 + q;
        float v0 = vs[lane][ml], v1 = vs[lane+32][ml];
        float s = v0 + v1;
        for (int o=16;o>0;o>>=1) s += __shfl_xor_sync(~0u,s,o);
        float mean = s*(1.f/64.f), d0 = v0-mean, d1 = v1-mean;
        float sq = d0*d0 + d1*d1;
        for (int o=16;o>0;o>>=1) sq += __shfl_xor_sync(~0u,sq,o);
        float rstd = rsqrtf(sq*(1.f/64.f) + 1e-5f);
        vs[lane][ml]    = d0*rstd*sc[lane]    + bi[lane];
        vs[lane+32][ml] = d1*rstd*sc[lane+32] + bi[lane+32];
    }
    __syncthreads();
    for (int j = 0; j < 8; j++) {
        int idx = tid + 256*j, k = idx>>5, ml = idx&31;
        outp[(size_t)b*64*NN + (size_t)k*NN + m0 + ml] = vs[k][ml];
    }
}

extern "C" void kernel_launch(void* const* d_in, const int* in_sizes, int n_in,
                              void* d_out, int out_size) {
    const float* x     = (const float*)d_in[0];
    const float* clus  = (const float*)d_in[1];
    const float* pi    = (const float*)d_in[2];
    const float* cov   = (const float*)d_in[3];
    const float* wproj = (const float*)d_in[4];
    const float* nts   = (const float*)d_in[5];
    const float* ntb   = (const float*)d_in[6];
    const float* pns   = (const float*)d_in[7];
    const float* pnb   = (const float*)d_in[8];
    float* out = (float*)d_out;
    float* out_outp = out;
    float* out_attn = out + 2359296;
    float* out_t    = out + 4718592;
    float* out_pi   = out + 4784128;
    float* out_cov  = out + 4785152;

    void *pP, *pA, *pY1, *pY2;
    cudaGetSymbolAddress(&pP, g_P);
    cudaGetSymbolAddress(&pA, g_Amask);
    cudaGetSymbolAddress(&pY1, g_Y1);
    cudaGetSymbolAddress(&pY2, g_Y2);

    k_zero<<<268, 256>>>();
    k_tmpl<<<1, 256>>>(clus, pi, cov, nts, ntb);
    k_proj<<<dim3(18, 16), 256>>>(x, wproj);
    k_softmax<<<dim3(72, 16), 256>>>(out_attn);
    k_tnewgemm<<<dim3(9, 16), 256>>>();
    k_stats<<<16, 64>>>(out_t, out_pi, out_cov);
    k_table<<<9, 256>>>();
    k_mcol<<<1, 256>>>();
    k_buildA<<<dim3(9, 2304), 256>>>();
    k_sgemm<<<dim3(18, 8), 256>>>((const float*)pP, (const float*)pA, (float*)pY1);
    k_sgemm<<<dim3(18, 8), 256>>>((const float*)pY1, (const float*)pA, (float*)pY2);
    k_finalln<<<dim3(72, 16), 256>>>(pns, pnb, out_outp);
}

// round 11
// speedup vs baseline: 2.2891x; 2.2891x over previous
#include <cuda_runtime.h>
#include <cuda_bf16.h>
#include <math.h>
#include <stdint.h>

#define BB 16
#define NN 2304
#define HH 48
#define CIN 256
#define GM 1024

__device__ float  g_xf[BB*NN*64];
__device__ float  g_x2[BB*NN];
__device__ float2 g_tsp[64*32];
__device__ float  g_c0[64], g_c1[64], g_c2[64];
__device__ float  g_P[GM*NN];
__device__ float  g_M[BB*64*64];
__device__ float  g_colsum[GM], g_S[GM], g_pisum[GM];
__device__ float  g_T[HH*HH];
__device__ float  g_rcol[NN];
__device__ float  g_Y1[GM*NN];
__device__ float  g_Y2[GM*NN];
/* plain row-major bf16 split operands */
__device__ __nv_bfloat16 g_Ph[GM*NN], g_Pl[GM*NN];       /* P hi/lo  [1024][2304] */
__device__ __nv_bfloat16 g_Bh[NN*NN], g_Bl[NN*NN];       /* B^T hi/lo [2304][2304] (row=out pixel, col=k) */
__device__ __nv_bfloat16 g_Yh[GM*NN], g_Yl[GM*NN];       /* Y1 hi/lo */

/* ---------------- helpers ---------------- */
__device__ __forceinline__ unsigned int smem_u32(const void* p) {
    unsigned int a;
    asm("{ .reg .u64 t; cvta.to.shared.u64 t, %1; cvt.u32.u64 %0, t; }" : "=r"(a) : "l"(p));
    return a;
}
#define CP16(sa, gp) asm volatile("cp.async.cg.shared.global [%0], [%1], 16;" :: "r"(sa), "l"(gp) : "memory")
#define CP_COMMIT()  asm volatile("cp.async.commit_group;" ::: "memory")
#define CP_WAIT0()   asm volatile("cp.async.wait_group 0;" ::: "memory")

__device__ __forceinline__ void mma16816(float* c, const unsigned* a, const unsigned* b) {
    asm volatile("mma.sync.aligned.m16n8k16.row.col.f32.bf16.bf16.f32 "
                 "{%0,%1,%2,%3}, {%4,%5,%6,%7}, {%8,%9}, {%0,%1,%2,%3};"
                 : "+f"(c[0]), "+f"(c[1]), "+f"(c[2]), "+f"(c[3])
                 : "r"(a[0]), "r"(a[1]), "r"(a[2]), "r"(a[3]), "r"(b[0]), "r"(b[1]));
}

/* ---------------- small kernels (R5-passing versions) ---------------- */
__global__ void k_zero() {
    int i = blockIdx.x*256 + threadIdx.x;
    if (i < BB*64*64) g_M[i] = 0.f;
    else { int j = i - BB*64*64;
        if (j < GM) g_colsum[j] = 0.f;
        else if (j < 2*GM) g_S[j-GM] = 0.f;
        else if (j < 3*GM) g_pisum[j-2*GM] = 0.f; }
}

__global__ void k_tmpl(const float* __restrict__ clus, const float* __restrict__ pi,
                       const float* __restrict__ cov, const float* __restrict__ nts,
                       const float* __restrict__ ntb) {
    __shared__ float ts[64][65];
    int tid = threadIdx.x, w = tid>>5, lane = tid&31;
    for (int q = 0; q < 8; q++) {
        int k = w*8 + q;
        float v0 = clus[k*64+lane], v1 = clus[k*64+lane+32];
        float s = v0+v1;
        for (int o=16;o>0;o>>=1) s += __shfl_xor_sync(~0u,s,o);
        float mean = s*(1.f/64.f), d0 = v0-mean, d1 = v1-mean;
        float vs = d0*d0 + d1*d1;
        for (int o=16;o>0;o>>=1) vs += __shfl_xor_sync(~0u,vs,o);
        float rstd = rsqrtf(vs*(1.f/64.f) + 1e-5f);
        ts[k][lane]    = d0*rstd*nts[lane]    + ntb[lane];
        ts[k][lane+32] = d1*rstd*nts[lane+32] + ntb[lane+32];
    }
    __syncthreads();
    if (tid < 64) {
        float t2 = 0.f;
        for (int c = 0; c < 64; c++) { float v = ts[tid][c]; t2 = fmaf(v,v,t2); }
        float cv = cov[tid], c1 = 1.f/cv, c2 = 0.5f*c1;
        g_c1[tid] = c1; g_c2[tid] = c2;
        g_c0[tid] = logf(pi[tid]/sqrtf(cv)) - t2*c2;
    }
    __syncthreads();
    for (int j = 0; j < 8; j++) {
        int idx = tid + 256*j, c = idx>>5, l = idx&31;
        g_tsp[c*32+l] = make_float2(ts[l][c], ts[l+32][c]);
    }
}

__global__ __launch_bounds__(256)
void k_proj(const float* __restrict__ x, const float* __restrict__ w) {
    int b = blockIdx.y, n0 = blockIdx.x*128;
    __shared__ float Xs[16][128], Ws[64][20], xfs[128][65];
    int tid = threadIdx.x, tn = tid&31, tc = tid>>5;
    float acc[4][8];
    for (int q=0;q<4;q++) for (int r=0;r<8;r++) acc[q][r] = 0.f;
    const float* xb = x + ((size_t)b*CIN)*NN + n0;
    for (int it = 0; it < CIN/16; it++) {
        for (int j = 0; j < 2; j++) {
            int idx = tid + 256*j, r = idx>>5, c = (idx&31)<<2;
            *(float4*)&Xs[r][c] = *(const float4*)&xb[(it*16+r)*NN + c];
        }
        { int r = tid>>2, c = (tid&3)<<2;
          *(float4*)&Ws[r][c] = *(const float4*)&w[r*CIN + it*16 + c]; }
        __syncthreads();
        for (int ii = 0; ii < 16; ii++) {
            float xv[4], wv[8];
            for (int q=0;q<4;q++) xv[q] = Xs[ii][tn+32*q];
            for (int r=0;r<8;r++) wv[r] = Ws[tc+8*r][ii];
            for (int q=0;q<4;q++) for (int r=0;r<8;r++) acc[q][r] = fmaf(xv[q],wv[r],acc[q][r]);
        }
        __syncthreads();
    }
    for (int q=0;q<4;q++) for (int r=0;r<8;r++) xfs[tn+32*q][tc+8*r] = acc[q][r];
    __syncthreads();
    if (tid < 128) {
        float s = 0.f;
        for (int c = 0; c < 64; c++) { float v = xfs[tid][c]; s = fmaf(v,v,s); }
        g_x2[b*NN + n0 + tid] = s;
    }
    float* xfg = g_xf + (size_t)(b*NN+n0)*64;
    for (int j = 0; j < 32; j++) { int idx = tid + 256*j; xfg[idx] = xfs[idx>>6][idx&63]; }
}

__global__ __launch_bounds__(256)
void k_softmax(float* __restrict__ attn_out) {
    int b = blockIdx.y, n0 = blockIdx.x*32;
    __shared__ float xfs[32][64];
    __shared__ float2 tsp_s[64][32];
    __shared__ float attn_s[64][33], x2s[32], c0s[64], c1s[64], c2s[64];
    int tid = threadIdx.x;
    if (tid < 64) { c0s[tid]=g_c0[tid]; c1s[tid]=g_c1[tid]; c2s[tid]=g_c2[tid]; }
    if (tid < 32) x2s[tid] = g_x2[b*NN+n0+tid];
    { const float4* s = (const float4*)g_tsp; float4* d = (float4*)tsp_s;
      for (int j=0;j<4;j++) d[tid+256*j] = s[tid+256*j]; }
    { const float4* s = (const float4*)(g_xf + (size_t)(b*NN+n0)*64); float4* d = (float4*)xfs;
      d[tid] = s[tid]; d[tid+256] = s[tid+256]; }
    __syncthreads();
    int w = tid>>5, lane = tid&31;
    for (int q = 0; q < 4; q++) {
        int nl = w*4 + q;
        float x2v = x2s[nl], a0 = 0.f, a1 = 0.f;
        for (int c = 0; c < 64; c++) {
            float xc = xfs[nl][c]; float2 tv = tsp_s[c][lane];
            a0 = fmaf(xc, tv.x, a0); a1 = fmaf(xc, tv.y, a1);
        }
        float g0 = c0s[lane]    + a0*c1s[lane]    - x2v*c2s[lane];
        float g1 = c0s[lane+32] + a1*c1s[lane+32] - x2v*c2s[lane+32];
        float mx = fmaxf(g0, g1);
        for (int o=16;o>0;o>>=1) mx = fmaxf(mx, __shfl_xor_sync(~0u,mx,o));
        float e0 = __expf(g0-mx), e1 = __expf(g1-mx), s = e0+e1;
        for (int o=16;o>0;o>>=1) s += __shfl_xor_sync(~0u,s,o);
        float r = 1.f/s;
        attn_s[lane][nl] = e0*r; attn_s[lane+32][nl] = e1*r;
    }
    __syncthreads();
    if (tid < 64) {
        float cs = 0.f, ss = 0.f, ps = 0.f;
        for (int nl = 0; nl < 32; nl++) {
            float a = attn_s[tid][nl], ae = a + 1e-8f;
            ps += a; cs += ae; ss = fmaf(ae, x2s[nl], ss);
        }
        atomicAdd(&g_colsum[b*64+tid], cs);
        atomicAdd(&g_S[b*64+tid], ss);
        atomicAdd(&g_pisum[b*64+tid], ps);
    }
    float* pout = g_P + (size_t)(b*64)*NN + n0;
    float* aout = attn_out + (size_t)b*64*NN + n0;
    for (int j = 0; j < 8; j++) {
        int idx = tid + 256*j, k = idx>>5, ml = idx&31;
        float a = attn_s[k][ml];
        aout[(size_t)k*NN + ml] = a;
        pout[(size_t)k*NN + ml] = a + 1e-8f;
    }
}

__global__ __launch_bounds__(256)
void k_tnewgemm() {
    int b = blockIdx.y;
    __shared__ float Ps[64][33], Xs2[32][65];
    int tid = threadIdx.x, tx = tid&15, ty = tid>>4;
    float acc[4][4];
    for (int a=0;a<4;a++) for (int d=0;d<4;d++) acc[a][d] = 0.f;
    for (int st = 0; st < 8; st++) {
        int n0 = blockIdx.x*256 + st*32;
        for (int j = 0; j < 8; j++) {
            int idx = tid + 256*j;
            Ps[idx>>5][idx&31] = g_P[(size_t)(b*64 + (idx>>5))*NN + n0 + (idx&31)];
        }
        for (int j = 0; j < 8; j++) {
            int idx = tid + 256*j;
            Xs2[idx>>6][idx&63] = g_xf[((size_t)(b*NN+n0) + (idx>>6))*64 + (idx&63)];
        }
        __syncthreads();
        for (int nl = 0; nl < 32; nl++) {
            float kv[4], xv[4];
            for (int a=0;a<4;a++) kv[a] = Ps[ty+16*a][nl];
            for (int d=0;d<4;d++) xv[d] = Xs2[nl][tx+16*d];
            for (int a=0;a<4;a++) for (int d=0;d<4;d++) acc[a][d] = fmaf(kv[a],xv[d],acc[a][d]);
        }
        __syncthreads();
    }
    for (int a=0;a<4;a++) for (int d=0;d<4;d++)
        atomicAdd(&g_M[b*4096 + (ty+16*a)*64 + tx+16*d], acc[a][d]);
}

__global__ void k_stats(float* __restrict__ out_t, float* __restrict__ out_pi,
                        float* __restrict__ out_cov) {
    int b = blockIdx.x, k = threadIdx.x;
    float rc = 1.f/g_colsum[b*64+k], tn2 = 0.f;
    float* tout = out_t + (size_t)(b*64+k)*64;
    for (int c = 0; c < 64; c++) {
        float tv = g_M[b*4096 + k*64 + c]*rc;
        tout[c] = tv; tn2 = fmaf(tv,tv,tn2);
    }
    out_pi[b*64+k] = g_pisum[b*64+k]*(1.f/(float)NN);
    out_cov[b*64+k] = g_S[b*64+k]*rc - tn2;
}

__global__ void k_table() {
    int idx = blockIdx.x*256 + threadIdx.x;
    if (idx < HH*HH) {
        int di = idx/HH, dj = idx%HH;
        g_T[idx] = expf(-sqrtf((float)(di*di + dj*dj)));
    }
}

__global__ void k_mcol() {
    __shared__ float Ts[HH*HH], U[HH*HH];
    int tid = threadIdx.x;
    for (int i = tid; i < HH*HH; i += 256) Ts[i] = g_T[i];
    __syncthreads();
    for (int idx = tid; idx < HH*HH; idx += 256) {
        int di = idx/HH, jm = idx%HH; float s = 0.f;
        for (int j = 0; j < HH; j++) s += Ts[di*HH + abs(j-jm)];
        U[idx] = s;
    }
    __syncthreads();
    for (int idx = tid; idx < HH*HH; idx += 256) {
        int im = idx/HH, jm = idx%HH; float s = 0.f;
        for (int i = 0; i < HH; i++) s += U[abs(i-im)*HH + jm];
        g_rcol[idx] = 1.f/s;
    }
}

/* B^T[m][n] = mask[n][m] = T[|ni-mi|][|nj-mj|] * rcol[m], split hi/lo, row-major */
__global__ void k_buildB() {
    int idx = blockIdx.x*256 + threadIdx.x;
    int m = idx / NN, n = idx - m*NN;
    int mi = m/HH, mj = m - mi*HH, ni = n/HH, nj = n - ni*HH;
    float v = g_T[abs(ni-mi)*HH + abs(nj-mj)] * g_rcol[m];
    __nv_bfloat16 h = __float2bfloat16(v);
    g_Bh[idx] = h;
    g_Bl[idx] = __float2bfloat16(v - __bfloat162float(h));
}

/* split fp32 -> bf16 hi/lo, plain row-major */
__global__ void k_conv(const float* __restrict__ src, __nv_bfloat16* __restrict__ hi,
                       __nv_bfloat16* __restrict__ lo) {
    int idx = blockIdx.x*256 + threadIdx.x;
    float v = src[idx];
    __nv_bfloat16 h = __float2bfloat16(v);
    hi[idx] = h;
    lo[idx] = __float2bfloat16(v - __bfloat162float(h));
}

/* ------------ HMMA GEMM: C[1024x2304] = split(A)[1024x2304] @ split(B^T)[2304x2304]^T ------------ */
/* smem layout per stage (bf16 units, stride 40 per row of 32):
   AH@0, AL@5120, BH@10240, BL@15360; stage stride 20480 (40960 B). */
#define SA 40
#define STG 20480

__global__ __launch_bounds__(256, 1)
void k_hgemm(const __nv_bfloat16* __restrict__ Ah, const __nv_bfloat16* __restrict__ Al,
             float* __restrict__ C) {
    extern __shared__ __nv_bfloat16 sm[];
    int tid = threadIdx.x, wid = tid>>5, lane = tid&31;
    int g = lane>>2, tig = lane&3;
    int wm = wid&3, wn = wid>>2;                       /* 4 x 2 warps */
    int bm = blockIdx.y<<7, bn = blockIdx.x<<7;

    const __nv_bfloat16* gAh = Ah + (size_t)bm*NN;
    const __nv_bfloat16* gAl = Al + (size_t)bm*NN;
    const __nv_bfloat16* gBh = g_Bh + (size_t)bn*NN;
    const __nv_bfloat16* gBl = g_Bl + (size_t)bn*NN;

    float c[2][8][4];
#pragma unroll
    for (int i=0;i<2;i++)
#pragma unroll
        for (int j=0;j<8;j++)
#pragma unroll
            for (int q=0;q<4;q++) c[i][j][q] = 0.f;

    int lr = tid>>2, lc = (tid&3)*8;                    /* loader coords: 64 rows x 4 thr */
    unsigned int smbase = smem_u32(sm);

    /* async-load chunk ch into stage st */
    auto cp_load = [&](int ch, int st) {
        unsigned int sb = smbase + st*STG*2;
#pragma unroll
        for (int p = 0; p < 2; p++) {
            int row = lr + p*64;
            size_t go = (size_t)row*NN + ch*32 + lc;
            unsigned int so = (unsigned int)((row*SA + lc)*2);
            CP16(sb + 0*5120*2 + so, (const void*)(gAh + go));
            CP16(sb + 1*5120*2 + so, (const void*)(gAl + go));
            CP16(sb + 2*5120*2 + so, (const void*)(gBh + go));
            CP16(sb + 3*5120*2 + so, (const void*)(gBl + go));
        }
    };

    cp_load(0, 0);
    CP_COMMIT();
    CP_WAIT0();
    __syncthreads();

    for (int ch = 0; ch < 72; ch++) {
        int cur = ch & 1;
        if (ch + 1 < 72) { cp_load(ch+1, cur^1); CP_COMMIT(); }

        const __nv_bfloat16* S = sm + cur*STG;
#pragma unroll
        for (int kk = 0; kk < 2; kk++) {
            int bk = kk*16;
            unsigned ah[2][4], al[2][4];
#pragma unroll
            for (int tm = 0; tm < 2; tm++) {
                int br = wm*32 + tm*16;
                const __nv_bfloat16* A0 = S + (br+g)*SA + bk + 2*tig;
                const __nv_bfloat16* A8 = S + (br+g+8)*SA + bk + 2*tig;
                ah[tm][0] = *(const unsigned*)(A0);
                ah[tm][1] = *(const unsigned*)(A8);
                ah[tm][2] = *(const unsigned*)(A0 + 8);
                ah[tm][3] = *(const unsigned*)(A8 + 8);
                al[tm][0] = *(const unsigned*)(A0 + 5120);
                al[tm][1] = *(const unsigned*)(A8 + 5120);
                al[tm][2] = *(const unsigned*)(A0 + 8 + 5120);
                al[tm][3] = *(const unsigned*)(A8 + 8 + 5120);
            }
#pragma unroll
            for (int tn = 0; tn < 8; tn++) {
                int bc = wn*64 + tn*8;
                const __nv_bfloat16* B0 = S + 10240 + (bc+g)*SA + bk + 2*tig;
                unsigned bh[2], bl[2];
                bh[0] = *(const unsigned*)(B0);
                bh[1] = *(const unsigned*)(B0 + 8);
                bl[0] = *(const unsigned*)(B0 + 5120);
                bl[1] = *(const unsigned*)(B0 + 8 + 5120);
#pragma unroll
                for (int tm = 0; tm < 2; tm++) {
                    mma16816(c[tm][tn], ah[tm], bh);
                    mma16816(c[tm][tn], ah[tm], bl);
                    mma16816(c[tm][tn], al[tm], bh);
                }
            }
        }
        if (ch + 1 < 72) CP_WAIT0();
        __syncthreads();
    }

    /* epilogue */
#pragma unroll
    for (int tm = 0; tm < 2; tm++) {
        int r0 = bm + wm*32 + tm*16 + g;
#pragma unroll
        for (int tn = 0; tn < 8; tn++) {
            int col = bn + wn*64 + tn*8 + 2*tig;
            *(float2*)&C[(size_t)r0*NN + col]     = make_float2(c[tm][tn][0], c[tm][tn][1]);
            *(float2*)&C[(size_t)(r0+8)*NN + col] = make_float2(c[tm][tn][2], c[tm][tn][3]);
        }
    }
}

__global__ __launch_bounds__(256)
void k_finalln(const float* __restrict__ pns, const float* __restrict__ pnb,
               float* __restrict__ outp) {
    int b = blockIdx.y, m0 = blockIdx.x*32;
    __shared__ float vs[64][33], rcs[64], sc[64], bi[64];
    int tid = threadIdx.x;
    if (tid < 64) { rcs[tid] = 1.f/g_colsum[b*64+tid]; sc[tid] = pns[tid]; bi[tid] = pnb[tid]; }
    __syncthreads();
    for (int j = 0; j < 8; j++) {
        int idx = tid + 256*j, k = idx>>5, ml = idx&31;
        vs[k][ml] = g_Y2[(size_t)(b*64+k)*NN + m0 + ml]*rcs[k];
    }
    __syncthreads();
    int w = tid>>5, lane = tid&31;
    for (int q = 0; q < 4; q++) {
        int ml = w*4 + q;
        float v0 = vs[lane][ml], v1 = vs[lane+32][ml];
        float s = v0 + v1;
        for (int o=16;o>0;o>>=1) s += __shfl_xor_sync(~0u,s,o);
        float mean = s*(1.f/64.f), d0 = v0-mean, d1 = v1-mean;
        float sq = d0*d0 + d1*d1;
        for (int o=16;o>0;o>>=1) sq += __shfl_xor_sync(~0u,sq,o);
        float rstd = rsqrtf(sq*(1.f/64.f) + 1e-5f);
        vs[lane][ml]    = d0*rstd*sc[lane]    + bi[lane];
        vs[lane+32][ml] = d1*rstd*sc[lane+32] + bi[lane+32];
    }
    __syncthreads();
    for (int j = 0; j < 8; j++) {
        int idx = tid + 256*j, k = idx>>5, ml = idx&31;
        outp[(size_t)b*64*NN + (size_t)k*NN + m0 + ml] = vs[k][ml];
    }
}

extern "C" void kernel_launch(void* const* d_in, const int* in_sizes, int n_in,
                              void* d_out, int out_size) {
    const float* x     = (const float*)d_in[0];
    const float* clus  = (const float*)d_in[1];
    const float* pi    = (const float*)d_in[2];
    const float* cov   = (const float*)d_in[3];
    const float* wproj = (const float*)d_in[4];
    const float* nts   = (const float*)d_in[5];
    const float* ntb   = (const float*)d_in[6];
    const float* pns   = (const float*)d_in[7];
    const float* pnb   = (const float*)d_in[8];
    float* out = (float*)d_out;
    float* out_outp = out;
    float* out_attn = out + 2359296;
    float* out_t    = out + 4718592;
    float* out_pi   = out + 4784128;
    float* out_cov  = out + 4785152;

    void *pP, *pY1, *pY2, *pPh, *pPl, *pYh, *pYl;
    cudaGetSymbolAddress(&pP,  g_P);
    cudaGetSymbolAddress(&pY1, g_Y1);
    cudaGetSymbolAddress(&pY2, g_Y2);
    cudaGetSymbolAddress(&pPh, g_Ph);
    cudaGetSymbolAddress(&pPl, g_Pl);
    cudaGetSymbolAddress(&pYh, g_Yh);
    cudaGetSymbolAddress(&pYl, g_Yl);

    cudaFuncSetAttribute(k_hgemm, cudaFuncAttributeMaxDynamicSharedMemorySize, 81920);

    k_zero<<<268, 256>>>();
    k_tmpl<<<1, 256>>>(clus, pi, cov, nts, ntb);
    k_proj<<<dim3(18, 16), 256>>>(x, wproj);
    k_softmax<<<dim3(72, 16), 256>>>(out_attn);
    k_tnewgemm<<<dim3(9, 16), 256>>>();
    k_stats<<<16, 64>>>(out_t, out_pi, out_cov);
    k_table<<<9, 256>>>();
    k_mcol<<<1, 256>>>();
    k_buildB<<<20736, 256>>>();
    k_conv<<<9216, 256>>>((const float*)pP, (__nv_bfloat16*)pPh, (__nv_bfloat16*)pPl);
    k_hgemm<<<dim3(18, 8), 256, 81920>>>((const __nv_bfloat16*)pPh, (const __nv_bfloat16*)pPl, (float*)pY1);
    k_conv<<<9216, 256>>>((const float*)pY1, (__nv_bfloat16*)pYh, (__nv_bfloat16*)pYl);
    k_hgemm<<<dim3(18, 8), 256, 81920>>>((const __nv_bfloat16*)pYh, (const __nv_bfloat16*)pYl, (float*)pY2);
    k_finalln<<<dim3(72, 16), 256>>>(pns, pnb, out_outp);
}